// round 3
// baseline (speedup 1.0000x reference)
#include <cuda_runtime.h>
#include <math.h>

// Problem constants (fixed by the dataset)
#define NN   50000
#define EE   1600000
#define ETOT (EE + NN)   // edges + self-loops
#define GG   512
#define HC   32          // H*C
#define NC   2

// ---------------- scratch (device globals; no allocation allowed) ----------
__device__ float        g_deg  [NN];
__device__ float        g_x0   [NN * 3];
__device__ float        g_xcur [NN * HC];     // ELU(conv1) output -> conv2 input
__device__ float        g_xl   [NN * HC];
__device__ float        g_xr   [NN * HC];
__device__ float        g_out  [NN * HC];     // conv accumulator / final features
__device__ float        g_score[ETOT * 2];    // per-edge per-head score, reused as exp
__device__ unsigned int g_smax [NN * 2];      // float bits, monotone-mapped atomics
__device__ float        g_denom[NN * 2];
__device__ float        g_sums [GG * HC];
__device__ float        g_cnt  [GG];

static inline int div_up(int a, int b) { return (a + b - 1) / b; }

// ---------------- kernels ---------------------------------------------------

__global__ void k_zero_deg() {
    int i = blockIdx.x * blockDim.x + threadIdx.x;
    if (i < NN) g_deg[i] = 0.f;
}

__global__ void k_degree(const int* __restrict__ ei) {
    int e = blockIdx.x * blockDim.x + threadIdx.x;
    if (e < EE) {
        atomicAdd(&g_deg[ei[e]], 1.f);
        atomicAdd(&g_deg[ei[EE + e]], 1.f);
    }
}

__global__ void k_feat(const float* __restrict__ rf) {
    int n = blockIdx.x * blockDim.x + threadIdx.x;
    if (n < NN) {
        g_x0[n * 3 + 0] = 1.f;
        g_x0[n * 3 + 1] = g_deg[n];
        g_x0[n * 3 + 2] = rf[n];
    }
}

// xl = x @ Wl^T + bl ; xr = x @ Wr^T + br.  One thread per (node, out-chan).
// F==3 reads g_x0, F==32 reads g_xcur.
template <int F>
__global__ void k_lin(const float* __restrict__ Wl, const float* __restrict__ bl,
                      const float* __restrict__ Wr, const float* __restrict__ br) {
    int t = blockIdx.x * blockDim.x + threadIdx.x;
    if (t >= NN * HC) return;
    int n = t >> 5, o = t & 31;
    const float* x = (F == 3) ? (g_x0 + n * 3) : (g_xcur + n * HC);
    float al = bl[o], ar = br[o];
#pragma unroll
    for (int k = 0; k < F; k++) {
        float xv = x[k];
        al += Wl[o * F + k] * xv;
        ar += Wr[o * F + k] * xv;
    }
    g_xl[t] = al;
    g_xr[t] = ar;
}

__global__ void k_init_conv() {
    int i = blockIdx.x * blockDim.x + threadIdx.x;
    if (i < NN * HC) g_out[i] = 0.f;
    if (i < NN * 2) {
        g_smax[i]  = 0xff800000u;   // -inf
        g_denom[i] = 0.f;
    }
}

// Warp per edge: score[e][h] = sum_c leaky(xl[s]+xr[d]) * att ;  atomic segment-max.
__global__ void k_score(const int* __restrict__ ei, const float* __restrict__ att) {
    int gt = blockIdx.x * blockDim.x + threadIdx.x;
    int e = gt >> 5;
    if (e >= ETOT) return;
    int l = gt & 31;
    int s, d;
    if (e < EE) { s = ei[e]; d = ei[EE + e]; }
    else        { s = d = e - EE; }
    float m = g_xl[s * HC + l] + g_xr[d * HC + l];
    m = (m > 0.f) ? m : 0.2f * m;              // LeakyReLU(0.2)
    float v = m * att[l];                       // att is [H,C] row-major == att[l]
    v += __shfl_xor_sync(0xffffffffu, v, 8);
    v += __shfl_xor_sync(0xffffffffu, v, 4);
    v += __shfl_xor_sync(0xffffffffu, v, 2);
    v += __shfl_xor_sync(0xffffffffu, v, 1);
    if ((l & 15) == 0) {
        int h = l >> 4;
        g_score[e * 2 + h] = v;
        unsigned int* addr = &g_smax[d * 2 + h];
        if (v >= 0.f) atomicMax((int*)addr, __float_as_int(v));
        else          atomicMin(addr, __float_as_uint(v));
    }
}

// Thread per (edge, head): ex = exp(score - smax[d]); denom += ex; store ex.
__global__ void k_exp(const int* __restrict__ ei) {
    int i = blockIdx.x * blockDim.x + threadIdx.x;
    if (i >= ETOT * 2) return;
    int e = i >> 1, h = i & 1;
    int d = (e < EE) ? ei[EE + e] : (e - EE);
    float smax = __uint_as_float(g_smax[d * 2 + h]);
    float ex = expf(g_score[i] - smax);
    g_score[i] = ex;
    atomicAdd(&g_denom[d * 2 + h], ex);
}

// Warp per edge: out[d] += xl[s] * alpha
__global__ void k_agg(const int* __restrict__ ei) {
    int gt = blockIdx.x * blockDim.x + threadIdx.x;
    int e = gt >> 5;
    if (e >= ETOT) return;
    int l = gt & 31;
    int s, d;
    if (e < EE) { s = ei[e]; d = ei[EE + e]; }
    else        { s = d = e - EE; }
    int h = l >> 4;
    float alpha = g_score[e * 2 + h] / (g_denom[d * 2 + h] + 1e-16f);
    atomicAdd(&g_out[d * HC + l], g_xl[s * HC + l] * alpha);
}

// out + bias -> ELU -> dst (dst_sel: 0 -> g_xcur, 1 -> g_out in place)
__global__ void k_bias_elu(const float* __restrict__ bias, int dst_sel) {
    int t = blockIdx.x * blockDim.x + threadIdx.x;
    if (t >= NN * HC) return;
    float v = g_out[t] + bias[t & 31];
    v = (v > 0.f) ? v : expm1f(v);
    if (dst_sel == 0) g_xcur[t] = v;
    else              g_out[t]  = v;
}

__global__ void k_zero_pool() {
    int i = blockIdx.x * blockDim.x + threadIdx.x;
    if (i < GG * HC) g_sums[i] = 0.f;
    if (i < GG)      g_cnt[i]  = 0.f;
}

__global__ void k_pool(const int* __restrict__ batch) {
    int t = blockIdx.x * blockDim.x + threadIdx.x;
    if (t >= NN * HC) return;
    int n = t >> 5, o = t & 31;
    int g = batch[n];
    atomicAdd(&g_sums[g * HC + o], g_out[t]);
    if (o == 0) atomicAdd(&g_cnt[g], 1.f);
}

__global__ void k_head(const float* __restrict__ Wfc, const float* __restrict__ bfc,
                       float* __restrict__ out) {
    int g = blockIdx.x * blockDim.x + threadIdx.x;
    if (g >= GG) return;
    float inv = 1.f / fmaxf(g_cnt[g], 1.f);
    float l0 = bfc[0], l1 = bfc[1];
#pragma unroll
    for (int k = 0; k < HC; k++) {
        float p = g_sums[g * HC + k] * inv;
        l0 += Wfc[k] * p;
        l1 += Wfc[HC + k] * p;
    }
    float mx  = fmaxf(l0, l1);
    float lse = mx + logf(expf(l0 - mx) + expf(l1 - mx));
    out[g * 2 + 0] = l0 - lse;
    out[g * 2 + 1] = l1 - lse;
}

// ---------------- launch -----------------------------------------------------

extern "C" void kernel_launch(void* const* d_in, const int* in_sizes, int n_in,
                              void* d_out, int out_size) {
    const int* ei    = (const int*)d_in[0];    // int32 (JAX x64 disabled)
    const int* batch = (const int*)d_in[1];    // int32
    const float* rand_feat = (const float*)d_in[2];
    const float* W1l = (const float*)d_in[3];
    const float* b1l = (const float*)d_in[4];
    const float* W1r = (const float*)d_in[5];
    const float* b1r = (const float*)d_in[6];
    const float* att1 = (const float*)d_in[7];
    const float* bias1 = (const float*)d_in[8];
    const float* W2l = (const float*)d_in[9];
    const float* b2l = (const float*)d_in[10];
    const float* W2r = (const float*)d_in[11];
    const float* b2r = (const float*)d_in[12];
    const float* att2 = (const float*)d_in[13];
    const float* bias2 = (const float*)d_in[14];
    const float* Wfc = (const float*)d_in[15];
    const float* bfc = (const float*)d_in[16];
    float* out = (float*)d_out;

    const int B = 256;
    const int gNode   = div_up(NN, B);
    const int gEdge   = div_up(EE, B);
    const int gNodeHC = div_up(NN * HC, B);
    const int gEdgeW  = div_up(ETOT * 32, B);   // warp per edge
    const int gEH     = div_up(ETOT * 2, B);

    // degree + input features
    k_zero_deg<<<gNode, B>>>();
    k_degree<<<gEdge, B>>>(ei);
    k_feat<<<gNode, B>>>(rand_feat);

    // ---- conv1 ----
    k_lin<3><<<gNodeHC, B>>>(W1l, b1l, W1r, b1r);
    k_init_conv<<<gNodeHC, B>>>();
    k_score<<<gEdgeW, B>>>(ei, att1);
    k_exp<<<gEH, B>>>(ei);
    k_agg<<<gEdgeW, B>>>(ei);
    k_bias_elu<<<gNodeHC, B>>>(bias1, 0);   // -> g_xcur

    // ---- conv2 ----
    k_lin<32><<<gNodeHC, B>>>(W2l, b2l, W2r, b2r);
    k_init_conv<<<gNodeHC, B>>>();
    k_score<<<gEdgeW, B>>>(ei, att2);
    k_exp<<<gEH, B>>>(ei);
    k_agg<<<gEdgeW, B>>>(ei);
    k_bias_elu<<<gNodeHC, B>>>(bias2, 1);   // -> g_out (in place)

    // ---- pool + head ----
    k_zero_pool<<<div_up(GG * HC, B), B>>>();
    k_pool<<<gNodeHC, B>>>(batch);
    k_head<<<div_up(GG, B), B>>>(Wfc, bfc, out);
}

// round 4
// speedup vs baseline: 1.6715x; 1.6715x over previous
#include <cuda_runtime.h>
#include <math.h>

// Problem constants (fixed by the dataset)
#define NN   50000
#define EE   1600000
#define ETOT (EE + NN)   // edges + self-loops
#define GG   512
#define HC   32          // H*C

// ---------------- scratch (device globals; no allocation allowed) ----------
__device__ __align__(16) float g_deg  [NN];
__device__ __align__(16) float g_x0   [NN * 3];
__device__ __align__(16) float g_xcur [NN * HC];
__device__ __align__(16) float g_xl   [NN * HC];
__device__ __align__(16) float g_xr   [NN * HC];
__device__ __align__(16) float g_out  [NN * HC];
__device__ __align__(16) float g_score[ETOT * 2];
__device__ unsigned int        g_smax [NN * 2];
__device__ __align__(16) float g_denom[NN * 2];
__device__ __align__(16) float g_sums [GG * HC];
__device__ __align__(16) float g_cnt  [GG];

static inline int div_up(int a, int b) { return (a + b - 1) / b; }

__device__ __forceinline__ void red4(float* p, float4 v) {
    asm volatile("red.global.add.v4.f32 [%0], {%1,%2,%3,%4};"
                 :: "l"(p), "f"(v.x), "f"(v.y), "f"(v.z), "f"(v.w) : "memory");
}

// ---------------- kernels ---------------------------------------------------

__global__ void k_zero_deg() {
    int i = blockIdx.x * blockDim.x + threadIdx.x;
    if (i < NN) g_deg[i] = 0.f;
}

__global__ void k_degree(const int* __restrict__ ei) {
    int e = blockIdx.x * blockDim.x + threadIdx.x;
    if (e < EE) {
        atomicAdd(&g_deg[ei[e]], 1.f);
        atomicAdd(&g_deg[ei[EE + e]], 1.f);
    }
}

__global__ void k_feat(const float* __restrict__ rf) {
    int n = blockIdx.x * blockDim.x + threadIdx.x;
    if (n < NN) {
        g_x0[n * 3 + 0] = 1.f;
        g_x0[n * 3 + 1] = g_deg[n];
        g_x0[n * 3 + 2] = rf[n];
    }
}

// xl = x @ Wl^T + bl ; xr = x @ Wr^T + br.  One thread per (node, out-chan).
template <int F>
__global__ void k_lin(const float* __restrict__ Wl, const float* __restrict__ bl,
                      const float* __restrict__ Wr, const float* __restrict__ br) {
    int t = blockIdx.x * blockDim.x + threadIdx.x;
    if (t >= NN * HC) return;
    int n = t >> 5, o = t & 31;
    const float* x = (F == 3) ? (g_x0 + n * 3) : (g_xcur + n * HC);
    float al = bl[o], ar = br[o];
#pragma unroll
    for (int k = 0; k < F; k++) {
        float xv = x[k];
        al += Wl[o * F + k] * xv;
        ar += Wr[o * F + k] * xv;
    }
    g_xl[t] = al;
    g_xr[t] = ar;
}

__global__ void k_init_conv() {
    int i = blockIdx.x * blockDim.x + threadIdx.x;
    if (i < NN * HC) g_out[i] = 0.f;
    if (i < NN * 2) {
        g_smax[i]  = 0xff800000u;   // -inf
        g_denom[i] = 0.f;
    }
}

// 4 edges per warp, 8 lanes per edge, float4 per lane.
// score[e][h] = sum_c leaky(xl[s]+xr[d])_c * att_c ;  atomic segment-max per dst.
__global__ void k_score4(const int* __restrict__ ei, const float* __restrict__ att) {
    int t = blockIdx.x * blockDim.x + threadIdx.x;
    int e = t >> 3;
    if (e >= ETOT) return;
    int j = t & 7;                 // lane within edge (channel group 4j..4j+3)
    int s, d;
    if (e < EE) { s = ei[e]; d = ei[EE + e]; }
    else        { s = d = e - EE; }
    const float4* xl4 = (const float4*)g_xl;
    const float4* xr4 = (const float4*)g_xr;
    float4 a = xl4[s * 8 + j];
    float4 b = xr4[d * 8 + j];
    float4 w = ((const float4*)att)[j];
    float m0 = a.x + b.x, m1 = a.y + b.y, m2 = a.z + b.z, m3 = a.w + b.w;
    m0 = (m0 > 0.f) ? m0 : 0.2f * m0;
    m1 = (m1 > 0.f) ? m1 : 0.2f * m1;
    m2 = (m2 > 0.f) ? m2 : 0.2f * m2;
    m3 = (m3 > 0.f) ? m3 : 0.2f * m3;
    float v = m0 * w.x + m1 * w.y + m2 * w.z + m3 * w.w;
    v += __shfl_xor_sync(0xffffffffu, v, 1);
    v += __shfl_xor_sync(0xffffffffu, v, 2);
    if ((j & 3) == 0) {            // j==0 -> head0, j==4 -> head1
        int h = j >> 2;
        g_score[e * 2 + h] = v;
        unsigned int* addr = &g_smax[d * 2 + h];
        if (v >= 0.f) atomicMax((int*)addr, __float_as_int(v));
        else          atomicMin(addr, __float_as_uint(v));
    }
}

// 4 edges per warp: ex = exp(score - smax[d]); out[d] += xl[s]*ex (v4 RED);
// denom[d][h] += ex.  Normalization happens in k_fin.
__global__ void k_expagg(const int* __restrict__ ei) {
    int t = blockIdx.x * blockDim.x + threadIdx.x;
    int e = t >> 3;
    if (e >= ETOT) return;
    int j = t & 7;
    int l = threadIdx.x & 31;
    int s, d;
    if (e < EE) { s = ei[e]; d = ei[EE + e]; }
    else        { s = d = e - EE; }
    float ex = 0.f;
    if ((j & 3) == 0) {
        int h = j >> 2;
        float smax = __uint_as_float(g_smax[d * 2 + h]);
        ex = expf(g_score[e * 2 + h] - smax);
        atomicAdd(&g_denom[d * 2 + h], ex);
    }
    ex = __shfl_sync(0xffffffffu, ex, l & 28);  // broadcast from head leader
    const float4* xl4 = (const float4*)g_xl;
    float4 a = xl4[s * 8 + j];
    float4 r = make_float4(a.x * ex, a.y * ex, a.z * ex, a.w * ex);
    red4(&g_out[d * HC + 4 * j], r);
}

// out/denom + bias -> ELU -> dst (dst_sel: 0 -> g_xcur, 1 -> g_out in place)
__global__ void k_fin(const float* __restrict__ bias, int dst_sel) {
    int t = blockIdx.x * blockDim.x + threadIdx.x;
    if (t >= NN * HC) return;
    int n = t >> 5, o = t & 31, h = o >> 4;
    float v = g_out[t] / (g_denom[n * 2 + h] + 1e-16f) + bias[o];
    v = (v > 0.f) ? v : expm1f(v);
    if (dst_sel == 0) g_xcur[t] = v;
    else              g_out[t]  = v;
}

__global__ void k_zero_pool() {
    int i = blockIdx.x * blockDim.x + threadIdx.x;
    if (i < GG * HC) g_sums[i] = 0.f;
    if (i < GG)      g_cnt[i]  = 0.f;
}

__global__ void k_pool4(const int* __restrict__ batch) {
    int t = blockIdx.x * blockDim.x + threadIdx.x;
    if (t >= NN * 8) return;
    int n = t >> 3, j = t & 7;
    int g = batch[n];
    const float4* out4 = (const float4*)g_out;
    red4(&g_sums[g * HC + 4 * j], out4[n * 8 + j]);
    if (j == 0) atomicAdd(&g_cnt[g], 1.f);
}

__global__ void k_head(const float* __restrict__ Wfc, const float* __restrict__ bfc,
                       float* __restrict__ out) {
    int g = blockIdx.x * blockDim.x + threadIdx.x;
    if (g >= GG) return;
    float inv = 1.f / fmaxf(g_cnt[g], 1.f);
    float l0 = bfc[0], l1 = bfc[1];
#pragma unroll
    for (int k = 0; k < HC; k++) {
        float p = g_sums[g * HC + k] * inv;
        l0 += Wfc[k] * p;
        l1 += Wfc[HC + k] * p;
    }
    float mx  = fmaxf(l0, l1);
    float lse = mx + logf(expf(l0 - mx) + expf(l1 - mx));
    out[g * 2 + 0] = l0 - lse;
    out[g * 2 + 1] = l1 - lse;
}

// ---------------- launch -----------------------------------------------------

extern "C" void kernel_launch(void* const* d_in, const int* in_sizes, int n_in,
                              void* d_out, int out_size) {
    const int* ei    = (const int*)d_in[0];
    const int* batch = (const int*)d_in[1];
    const float* rand_feat = (const float*)d_in[2];
    const float* W1l = (const float*)d_in[3];
    const float* b1l = (const float*)d_in[4];
    const float* W1r = (const float*)d_in[5];
    const float* b1r = (const float*)d_in[6];
    const float* att1 = (const float*)d_in[7];
    const float* bias1 = (const float*)d_in[8];
    const float* W2l = (const float*)d_in[9];
    const float* b2l = (const float*)d_in[10];
    const float* W2r = (const float*)d_in[11];
    const float* b2r = (const float*)d_in[12];
    const float* att2 = (const float*)d_in[13];
    const float* bias2 = (const float*)d_in[14];
    const float* Wfc = (const float*)d_in[15];
    const float* bfc = (const float*)d_in[16];
    float* out = (float*)d_out;

    const int B = 256;
    const int gNode   = div_up(NN, B);
    const int gEdge   = div_up(EE, B);
    const int gNodeHC = div_up(NN * HC, B);
    const int gEdge8  = div_up(ETOT * 8, B);    // 8 lanes per edge

    // degree + input features
    k_zero_deg<<<gNode, B>>>();
    k_degree<<<gEdge, B>>>(ei);
    k_feat<<<gNode, B>>>(rand_feat);

    // ---- conv1 ----
    k_lin<3><<<gNodeHC, B>>>(W1l, b1l, W1r, b1r);
    k_init_conv<<<gNodeHC, B>>>();
    k_score4<<<gEdge8, B>>>(ei, att1);
    k_expagg<<<gEdge8, B>>>(ei);
    k_fin<<<gNodeHC, B>>>(bias1, 0);   // -> g_xcur

    // ---- conv2 ----
    k_lin<32><<<gNodeHC, B>>>(W2l, b2l, W2r, b2r);
    k_init_conv<<<gNodeHC, B>>>();
    k_score4<<<gEdge8, B>>>(ei, att2);
    k_expagg<<<gEdge8, B>>>(ei);
    k_fin<<<gNodeHC, B>>>(bias2, 1);   // -> g_out (in place)

    // ---- pool + head ----
    k_zero_pool<<<div_up(GG * HC, B), B>>>();
    k_pool4<<<div_up(NN * 8, B), B>>>(batch);
    k_head<<<div_up(GG, B), B>>>(Wfc, bfc, out);
}